// round 16
// baseline (speedup 1.0000x reference)
#include <cuda_runtime.h>
#include <cuda_bf16.h>

#define NB 16384
#define LL 1024

// Single packed accumulator: bits[0:15)=block count, bits[15:64)=sum in Q16
// fixed point (mod 2^49, two's complement). 0 at kernel entry; watcher restores.
__device__ unsigned long long g_pack = 0ULL;

__global__ __launch_bounds__(256) void bicut_fused(
    const float4* __restrict__ out4,   // output as float4: row stride 512
    const int4*   __restrict__ lab4,   // labels (int32) as int4: row stride 256
    float*        __restrict__ out)
{
    const int row = blockIdx.x;
    const int tid = threadIdx.x;
    const int j0  = tid * 4;

    // ---- load output pairs (positions j0..j0+3) and labels, evict-first ----
    const float4* orow = out4 + (size_t)row * 512;
    float4 a = __ldcs(orow + tid * 2);       // j0, j0+1 : (o0,o1,o0,o1)
    float4 b = __ldcs(orow + tid * 2 + 1);   // j0+2, j0+3
    int4   l = __ldcs(lab4 + (size_t)row * 256 + tid);

    // ---- last index with o1 <= o0 (argmax tie-break: temp=1 iff o1 > o0) ----
    int tz = -1;
    if (a.y <= a.x) tz = j0;
    if (a.w <= a.z) tz = j0 + 1;
    if (b.y <= b.x) tz = j0 + 2;
    if (b.w <= b.z) tz = j0 + 3;

    __shared__ int   smax[8];
    __shared__ float ssum[8];

    int m = __reduce_max_sync(0xffffffffu, tz);
    if ((tid & 31) == 0) smax[tid >> 5] = m;
    __syncthreads();
    if (tid < 32) {
        int v = (tid < 8) ? smax[tid] : -1;
        v = __reduce_max_sync(0xffffffffu, v);
        if (tid == 0) smax[0] = v;
    }
    __syncthreads();
    int idx = smax[0];
    if (idx < 0) idx = LL - 1;   // all-continue row: mask is all ones anyway

    // ---- masked weighted sum ----
    const float INV_ALPHA = 1.0f / 0.65f;
    float o1v[4] = {a.y, a.w, b.y, b.w};
    int   lv[4]  = {l.x, l.y, l.z, l.w};

    float s = 0.0f;
    #pragma unroll
    for (int k = 0; k < 4; k++) {
        int j = j0 + k;
        if (j <= idx) {
            float jf = (float)j;
            float r = (lv[k] == 1) ? (-1.0f / __log2f(jf + 2.0f))
                                   : ((jf + 1.0f) * INV_ALPHA);
            s += o1v[k] * r;
        }
    }

    // ---- block sum -> ONE relaxed RED carrying (count | Q16 sum) ----
    #pragma unroll
    for (int o = 16; o; o >>= 1) s += __shfl_xor_sync(0xffffffffu, s, o);
    if ((tid & 31) == 0) ssum[tid >> 5] = s;
    __syncthreads();
    if (tid == 0) {
        float t = 0.0f;
        #pragma unroll
        for (int w = 0; w < 8; w++) t += ssum[w];
        long long q = llrintf(t * 65536.0f);               // Q16 fixed point
        unsigned long long v = ((unsigned long long)q << 15) + 1ULL;
        asm volatile("red.relaxed.gpu.global.add.u64 [%0], %1;"
                     :: "l"(&g_pack), "l"(v) : "memory");   // fire-and-forget
    }

    // ---- watcher: poll the single word; its value IS the complete result ----
    if (blockIdx.x == NB - 1 && tid == 0) {
        unsigned long long v;
        do {
            __nanosleep(64);
            asm volatile("ld.relaxed.gpu.global.u64 %0, [%1];"
                         : "=l"(v) : "l"(&g_pack) : "memory");
        } while ((v & 0x7FFFULL) < (unsigned long long)NB);
        // count==NB => all 16384 adds are in this very value (single-word atomicity)
        long long q = ((long long)v) >> 15;   // sign bit 48 sits at bit 63
        out[0] = (float)((double)q * (1.0 / (65536.0 * (double)NB)));
        g_pack = 0ULL;                        // restore for next graph replay
    }
}

extern "C" void kernel_launch(void* const* d_in, const int* in_sizes, int n_in,
                              void* d_out, int out_size) {
    const float4* out4 = (const float4*)d_in[0];
    const int4*   lab4 = (const int4*)d_in[1];
    float* out = (float*)d_out;

    bicut_fused<<<NB, 256>>>(out4, lab4, out);
}

// round 17
// speedup vs baseline: 1.0692x; 1.0692x over previous
#include <cuda_runtime.h>
#include <cuda_bf16.h>

#define NB 16384
#define LL 1024
#define RPB 2
#define GRID (NB / RPB)   // 8192

// Single packed accumulator: bits[0:15)=block count, bits[15:64)=sum in Q16
// fixed point (mod 2^49). 0 at kernel entry; watcher restores.
__device__ unsigned long long g_pack = 0ULL;

__global__ __launch_bounds__(256) void bicut_fused(
    const float4* __restrict__ out4,   // output as float4: row stride 512
    const int4*   __restrict__ lab4,   // labels (int32) as int4: row stride 256
    float*        __restrict__ out)
{
    const int tid = threadIdx.x;
    const int j0  = tid * 4;

    // ---- front-batch BOTH rows' loads (MLP = 6/thread) ----
    const size_t r0 = (size_t)blockIdx.x * RPB;
    const float4* orow0 = out4 + r0 * 512;
    const float4* orow1 = orow0 + 512;
    float4 a0 = orow0[tid * 2];
    float4 b0 = orow0[tid * 2 + 1];
    float4 a1 = orow1[tid * 2];
    float4 b1 = orow1[tid * 2 + 1];
    int4   l0 = lab4[r0 * 256 + tid];
    int4   l1 = lab4[r0 * 256 + 256 + tid];

    // ---- r-value candidates: pure function of tid — computed ONCE for both
    // rows, and issued in the load-latency shadow ----
    const float INV_ALPHA = 1.0f / 0.65f;
    float rA[4], rB[4];
    #pragma unroll
    for (int k = 0; k < 4; k++) {
        float jf = (float)(j0 + k);
        rA[k] = -1.0f / __log2f(jf + 2.0f);   // label==1 value
        rB[k] = (jf + 1.0f) * INV_ALPHA;      // label==0 value
    }

    // ---- last-zero index per row (argmax tie: temp=1 iff o1 > o0) ----
    int tz0 = -1, tz1 = -1;
    if (a0.y <= a0.x) tz0 = j0;
    if (a0.w <= a0.z) tz0 = j0 + 1;
    if (b0.y <= b0.x) tz0 = j0 + 2;
    if (b0.w <= b0.z) tz0 = j0 + 3;
    if (a1.y <= a1.x) tz1 = j0;
    if (a1.w <= a1.z) tz1 = j0 + 1;
    if (b1.y <= b1.x) tz1 = j0 + 2;
    if (b1.w <= b1.z) tz1 = j0 + 3;

    __shared__ int   smax[2][8];
    __shared__ float ssum[8];

    int m0 = __reduce_max_sync(0xffffffffu, tz0);
    int m1 = __reduce_max_sync(0xffffffffu, tz1);
    if ((tid & 31) == 0) { smax[0][tid >> 5] = m0; smax[1][tid >> 5] = m1; }
    __syncthreads();
    if (tid < 32) {
        int v0 = (tid < 8) ? smax[0][tid] : -1;
        int v1 = (tid < 8) ? smax[1][tid] : -1;
        v0 = __reduce_max_sync(0xffffffffu, v0);
        v1 = __reduce_max_sync(0xffffffffu, v1);
        if (tid == 0) { smax[0][0] = v0; smax[1][0] = v1; }
    }
    __syncthreads();
    int idx0 = smax[0][0]; if (idx0 < 0) idx0 = LL - 1;
    int idx1 = smax[1][0]; if (idx1 < 0) idx1 = LL - 1;

    // ---- masked weighted sums for both rows, reusing rA/rB ----
    float o1v0[4] = {a0.y, a0.w, b0.y, b0.w};
    float o1v1[4] = {a1.y, a1.w, b1.y, b1.w};
    int   lv0[4]  = {l0.x, l0.y, l0.z, l0.w};
    int   lv1[4]  = {l1.x, l1.y, l1.z, l1.w};

    float s = 0.0f;
    #pragma unroll
    for (int k = 0; k < 4; k++) {
        int j = j0 + k;
        float r0v = (lv0[k] == 1) ? rA[k] : rB[k];
        float r1v = (lv1[k] == 1) ? rA[k] : rB[k];
        if (j <= idx0) s += o1v0[k] * r0v;
        if (j <= idx1) s += o1v1[k] * r1v;
    }

    // ---- one block sum + ONE relaxed RED carrying (count | Q16 sum) ----
    #pragma unroll
    for (int o = 16; o; o >>= 1) s += __shfl_xor_sync(0xffffffffu, s, o);
    if ((tid & 31) == 0) ssum[tid >> 5] = s;
    __syncthreads();
    if (tid == 0) {
        float t = 0.0f;
        #pragma unroll
        for (int w = 0; w < 8; w++) t += ssum[w];
        long long q = llrintf(t * 65536.0f);               // Q16 fixed point
        unsigned long long v = ((unsigned long long)q << 15) + 1ULL;
        asm volatile("red.relaxed.gpu.global.add.u64 [%0], %1;"
                     :: "l"(&g_pack), "l"(v) : "memory");   // fire-and-forget
    }

    // ---- watcher: poll the single word; its value IS the complete result ----
    if (blockIdx.x == GRID - 1 && tid == 0) {
        unsigned long long v;
        do {
            __nanosleep(64);
            asm volatile("ld.relaxed.gpu.global.u64 %0, [%1];"
                         : "=l"(v) : "l"(&g_pack) : "memory");
        } while ((v & 0x7FFFULL) < (unsigned long long)GRID);
        long long q = ((long long)v) >> 15;   // sign bit 48 sits at bit 63
        out[0] = (float)((double)q * (1.0 / (65536.0 * (double)NB)));
        g_pack = 0ULL;                        // restore for next graph replay
    }
}

extern "C" void kernel_launch(void* const* d_in, const int* in_sizes, int n_in,
                              void* d_out, int out_size) {
    const float4* out4 = (const float4*)d_in[0];
    const int4*   lab4 = (const int4*)d_in[1];
    float* out = (float*)d_out;

    bicut_fused<<<GRID, 256>>>(out4, lab4, out);
}